// round 2
// baseline (speedup 1.0000x reference)
#include <cuda_runtime.h>
#include <cuda_bf16.h>

#define NNODES 50000
#define HIDDEN 128
#define MLPD   64

// Per-node precomputed table: T[n][0:64]  = emb[n] @ W1[0:128,:],
//                             T[n][64:128]= emb[n] @ W1[128:256,:]
__device__ float g_T[(size_t)NNODES * HIDDEN];
__device__ int g_is64;   // 1 if edge_index buffer is int64, 0 if int32

// ---------------------------------------------------------------------------
// Kernel 0: detect edge_index dtype. Deterministic: pure function of input.
// Reading 1024 int64 words (8 KB) is in-bounds for both interpretations.
// ---------------------------------------------------------------------------
__global__ void detect_kernel(const void* __restrict__ eidx, int twoE) {
    if (threadIdx.x == 0) {
        const long long* p = (const long long*)eidx;
        int n = twoE < 1024 ? twoE : 1024;
        int ok = 1;
        for (int i = 0; i < n; i++) {
            long long v = p[i];
            if (v < 0 || v >= NNODES) { ok = 0; break; }
        }
        g_is64 = ok;
    }
}

// ---------------------------------------------------------------------------
// Kernel 1: T = emb @ Wc   where Wc[k][c] = (c<64) ? W1[k][c] : W1[128+k][c-64]
// Block: 256 threads, tile = 32 nodes x 128 cols. Reg tile 4x4 per thread.
// ---------------------------------------------------------------------------
__global__ void __launch_bounds__(256, 2)
precompute_kernel(const float* __restrict__ emb, const float* __restrict__ W1) {
    extern __shared__ float smem[];
    float* sW = smem;              // [128][128] k-major
    float* sE = smem + 128 * 128;  // [32][128]  node-major

    const int t = threadIdx.x;
    const int n0 = blockIdx.x * 32;

    for (int i = t; i < 128 * 128; i += 256) {
        int k = i >> 7, c = i & 127;
        sW[i] = (c < MLPD) ? W1[k * MLPD + c] : W1[(HIDDEN + k) * MLPD + (c - MLPD)];
    }
    for (int i = t; i < 32 * 128; i += 256) {
        int node = i >> 7, k = i & 127;
        int gn = n0 + node;
        sE[i] = (gn < NNODES) ? emb[(size_t)gn * HIDDEN + k] : 0.0f;
    }
    __syncthreads();

    const int tx = t & 31;   // col group: cols tx*4 .. tx*4+3
    const int ty = t >> 5;   // node group: nodes ty*4 .. ty*4+3

    float acc[4][4];
#pragma unroll
    for (int i = 0; i < 4; i++)
#pragma unroll
        for (int j = 0; j < 4; j++) acc[i][j] = 0.0f;

#pragma unroll 4
    for (int k = 0; k < 128; k += 4) {
        float4 a[4], w[4];
#pragma unroll
        for (int i = 0; i < 4; i++)
            a[i] = *(const float4*)&sE[(ty * 4 + i) * 128 + k];
#pragma unroll
        for (int kk = 0; kk < 4; kk++)
            w[kk] = *(const float4*)&sW[(k + kk) * 128 + tx * 4];
#pragma unroll
        for (int i = 0; i < 4; i++) {
            acc[i][0] += a[i].x * w[0].x + a[i].y * w[1].x + a[i].z * w[2].x + a[i].w * w[3].x;
            acc[i][1] += a[i].x * w[0].y + a[i].y * w[1].y + a[i].z * w[2].y + a[i].w * w[3].y;
            acc[i][2] += a[i].x * w[0].z + a[i].y * w[1].z + a[i].z * w[2].z + a[i].w * w[3].z;
            acc[i][3] += a[i].x * w[0].w + a[i].y * w[1].w + a[i].z * w[2].w + a[i].w * w[3].w;
        }
    }

#pragma unroll
    for (int i = 0; i < 4; i++) {
        int gn = n0 + ty * 4 + i;
        if (gn < NNODES) {
            float4 v = make_float4(acc[i][0], acc[i][1], acc[i][2], acc[i][3]);
            *(float4*)&g_T[(size_t)gn * HIDDEN + tx * 4] = v;
        }
    }
}

// ---------------------------------------------------------------------------
// Kernel 2: per edge  logit = W2 . relu(T[src][0:64] + T[dst][64:128] + b1) + b2
// 8 threads per edge; each thread handles 8 contiguous h-columns (32B loads).
// ---------------------------------------------------------------------------
__global__ void __launch_bounds__(256)
edge_kernel(const void* __restrict__ eidx_raw,
            const float* __restrict__ b1, const float* __restrict__ W2,
            const float* __restrict__ b2, float* __restrict__ out, int E) {
    __shared__ float sB1[MLPD];
    __shared__ float sW2[MLPD];
    const int t = threadIdx.x;
    if (t < MLPD) sB1[t] = b1[t];
    else if (t < 2 * MLPD) sW2[t - MLPD] = W2[t - MLPD];
    __syncthreads();

    const int lane8 = t & 7;
    const int e = blockIdx.x * 32 + (t >> 3);
    if (e >= E) return;

    size_t src, dst;
    if (g_is64) {
        const long long* p = (const long long*)eidx_raw;
        src = (size_t)p[e];
        dst = (size_t)p[(size_t)E + e];
    } else {
        const int* p = (const int*)eidx_raw;
        src = (size_t)p[e];
        dst = (size_t)p[(size_t)E + e];
    }

    const float4* Ts = (const float4*)&g_T[src * HIDDEN + lane8 * 8];
    const float4* Td = (const float4*)&g_T[dst * HIDDEN + MLPD + lane8 * 8];
    float4 a0 = Ts[0], a1 = Ts[1];
    float4 c0 = Td[0], c1 = Td[1];
    float4 bb0 = *(const float4*)&sB1[lane8 * 8];
    float4 bb1 = *(const float4*)&sB1[lane8 * 8 + 4];
    float4 w0 = *(const float4*)&sW2[lane8 * 8];
    float4 w1 = *(const float4*)&sW2[lane8 * 8 + 4];

    float h0 = fmaxf(a0.x + c0.x + bb0.x, 0.0f);
    float h1 = fmaxf(a0.y + c0.y + bb0.y, 0.0f);
    float h2 = fmaxf(a0.z + c0.z + bb0.z, 0.0f);
    float h3 = fmaxf(a0.w + c0.w + bb0.w, 0.0f);
    float h4 = fmaxf(a1.x + c1.x + bb1.x, 0.0f);
    float h5 = fmaxf(a1.y + c1.y + bb1.y, 0.0f);
    float h6 = fmaxf(a1.z + c1.z + bb1.z, 0.0f);
    float h7 = fmaxf(a1.w + c1.w + bb1.w, 0.0f);
    float sum = h0 * w0.x + h1 * w0.y + h2 * w0.z + h3 * w0.w
              + h4 * w1.x + h5 * w1.y + h6 * w1.z + h7 * w1.w;

    sum += __shfl_down_sync(0xffffffffu, sum, 4, 8);
    sum += __shfl_down_sync(0xffffffffu, sum, 2, 8);
    sum += __shfl_down_sync(0xffffffffu, sum, 1, 8);

    if (lane8 == 0) out[e] = sum + __ldg(b2);
}

// ---------------------------------------------------------------------------
extern "C" void kernel_launch(void* const* d_in, const int* in_sizes, int n_in,
                              void* d_out, int out_size) {
    const float* node_emb = (const float*)d_in[0];
    const void*  eidx     = d_in[1];
    const float* W1       = (const float*)d_in[2];
    const float* b1       = (const float*)d_in[3];
    const float* W2       = (const float*)d_in[4];
    const float* b2       = (const float*)d_in[5];
    float*       out      = (float*)d_out;

    const int twoE = in_sizes[1];
    const int E = twoE / 2;

    const int smem = (128 * 128 + 32 * 128) * (int)sizeof(float);  // 80 KB
    cudaFuncSetAttribute(precompute_kernel,
                         cudaFuncAttributeMaxDynamicSharedMemorySize, smem);

    detect_kernel<<<1, 32>>>(eidx, twoE);
    precompute_kernel<<<(NNODES + 31) / 32, 256, smem>>>(node_emb, W1);
    edge_kernel<<<(E + 31) / 32, 256>>>(eidx, b1, W2, b2, out, E);
}

// round 3
// speedup vs baseline: 1.2105x; 1.2105x over previous
#include <cuda_runtime.h>
#include <cuda_bf16.h>

#define NNODES 50000
#define HIDDEN 128
#define MLPD   64

// Per-node precomputed table: T[n][0:64]  = emb[n] @ W1[0:128,:],
//                             T[n][64:128]= emb[n] @ W1[128:256,:]
__device__ float g_T[(size_t)NNODES * HIDDEN];
__device__ int g_is64;   // 1 if edge_index buffer is int64, 0 if int32

// ---- packed f32x2 helpers (sm_100+ only via PTX) ---------------------------
__device__ __forceinline__ unsigned long long pk2(float lo, float hi) {
    unsigned long long r;
    asm("mov.b64 %0, {%1,%2};" : "=l"(r) : "f"(lo), "f"(hi));
    return r;
}
__device__ __forceinline__ unsigned long long fma2(unsigned long long a,
                                                   unsigned long long b,
                                                   unsigned long long c) {
    unsigned long long d;
    asm("fma.rn.f32x2 %0, %1, %2, %3;" : "=l"(d) : "l"(a), "l"(b), "l"(c));
    return d;
}
__device__ __forceinline__ void upk2(unsigned long long v, float& lo, float& hi) {
    asm("mov.b64 {%0,%1}, %2;" : "=f"(lo), "=f"(hi) : "l"(v));
}

// ---------------------------------------------------------------------------
// Kernel 0: detect edge_index dtype (parallel probe; deterministic).
// Reading 1024 int64 words (8 KB) is in-bounds under both interpretations.
// ---------------------------------------------------------------------------
__global__ void detect_kernel(const long long* __restrict__ p, int twoE) {
    __shared__ int ok;
    if (threadIdx.x == 0) ok = 1;
    __syncthreads();
    int n = twoE < 1024 ? twoE : 1024;
    for (int i = threadIdx.x; i < n; i += 256) {
        long long v = p[i];
        if (v < 0 || v >= NNODES) ok = 0;
    }
    __syncthreads();
    if (threadIdx.x == 0) g_is64 = ok;
}

// ---------------------------------------------------------------------------
// Kernel 1: T = emb @ Wc   where Wc[k][c] = (c<64) ? W1[k][c] : W1[128+k][c-64]
// 256 threads, tile = 32 nodes x 128 cols, reg tile 4 nodes x 4 cols, FFMA2.
// ---------------------------------------------------------------------------
__global__ void __launch_bounds__(256, 2)
precompute_kernel(const float* __restrict__ emb, const float* __restrict__ W1) {
    extern __shared__ float smem[];
    float* sW = smem;              // [128][128] k-major
    float* sE = smem + 128 * 128;  // [32][128]  node-major

    const int t = threadIdx.x;
    const int n0 = blockIdx.x * 32;

    // Wc loader, float4 vectorized: 4096 float4s
    for (int i = t; i < 128 * 32; i += 256) {
        int k = i >> 5, c4 = i & 31;
        const float* srcp = (c4 < 16) ? (W1 + k * MLPD + c4 * 4)
                                      : (W1 + (HIDDEN + k) * MLPD + (c4 - 16) * 4);
        ((float4*)sW)[i] = *(const float4*)srcp;
    }
    // emb tile loader, float4: 1024 float4s
    for (int i = t; i < 32 * 32; i += 256) {
        int node = i >> 5, c4 = i & 31;
        int gn = n0 + node;
        ((float4*)sE)[i] = (gn < NNODES)
            ? *(const float4*)&emb[(size_t)gn * HIDDEN + c4 * 4]
            : make_float4(0.f, 0.f, 0.f, 0.f);
    }
    __syncthreads();

    const int tx = t & 31;   // col group: cols tx*4 .. tx*4+3
    const int ty = t >> 5;   // node group: nodes ty*4 .. ty*4+3

    unsigned long long acc01[4], acc23[4];
    const unsigned long long z = pk2(0.f, 0.f);
#pragma unroll
    for (int i = 0; i < 4; i++) { acc01[i] = z; acc23[i] = z; }

#pragma unroll 4
    for (int k = 0; k < 128; k += 4) {
        float4 a[4], w[4];
#pragma unroll
        for (int i = 0; i < 4; i++)
            a[i] = *(const float4*)&sE[(ty * 4 + i) * 128 + k];
#pragma unroll
        for (int kk = 0; kk < 4; kk++)
            w[kk] = *(const float4*)&sW[(k + kk) * 128 + tx * 4];

        unsigned long long wlo[4], whi[4];
#pragma unroll
        for (int kk = 0; kk < 4; kk++) {
            wlo[kk] = pk2(w[kk].x, w[kk].y);
            whi[kk] = pk2(w[kk].z, w[kk].w);
        }
#pragma unroll
        for (int i = 0; i < 4; i++) {
            unsigned long long aa;
            aa = pk2(a[i].x, a[i].x);
            acc01[i] = fma2(aa, wlo[0], acc01[i]);
            acc23[i] = fma2(aa, whi[0], acc23[i]);
            aa = pk2(a[i].y, a[i].y);
            acc01[i] = fma2(aa, wlo[1], acc01[i]);
            acc23[i] = fma2(aa, whi[1], acc23[i]);
            aa = pk2(a[i].z, a[i].z);
            acc01[i] = fma2(aa, wlo[2], acc01[i]);
            acc23[i] = fma2(aa, whi[2], acc23[i]);
            aa = pk2(a[i].w, a[i].w);
            acc01[i] = fma2(aa, wlo[3], acc01[i]);
            acc23[i] = fma2(aa, whi[3], acc23[i]);
        }
    }

#pragma unroll
    for (int i = 0; i < 4; i++) {
        int gn = n0 + ty * 4 + i;
        if (gn < NNODES) {
            float4 v;
            upk2(acc01[i], v.x, v.y);
            upk2(acc23[i], v.z, v.w);
            *(float4*)&g_T[(size_t)gn * HIDDEN + tx * 4] = v;
        }
    }
}

// ---------------------------------------------------------------------------
// Kernel 2: per edge  logit = W2 . relu(T[src][0:64] + T[dst][64:128] + b1) + b2
// 8 threads per edge; leader loads indices, broadcasts offsets via shfl.
// ---------------------------------------------------------------------------
__global__ void __launch_bounds__(256)
edge_kernel(const void* __restrict__ eidx_raw,
            const float* __restrict__ b1, const float* __restrict__ W2,
            const float* __restrict__ b2, float* __restrict__ out, int E) {
    __shared__ float sB1[MLPD];
    __shared__ float sW2[MLPD];
    const int t = threadIdx.x;
    if (t < MLPD) sB1[t] = b1[t];
    else if (t < 2 * MLPD) sW2[t - MLPD] = W2[t - MLPD];
    __syncthreads();

    const int lane8 = t & 7;
    const int e = blockIdx.x * 32 + (t >> 3);
    if (e >= E) return;

    int offS = 0, offD = 0;
    if (lane8 == 0) {
        if (g_is64) {
            const long long* p = (const long long*)eidx_raw;
            offS = (int)p[e] * HIDDEN;
            offD = (int)p[(size_t)E + e] * HIDDEN + MLPD;
        } else {
            const int* p = (const int*)eidx_raw;
            offS = p[e] * HIDDEN;
            offD = p[(size_t)E + e] * HIDDEN + MLPD;
        }
    }
    offS = __shfl_sync(0xffffffffu, offS, 0, 8);
    offD = __shfl_sync(0xffffffffu, offD, 0, 8);

    const float4* Ts = (const float4*)&g_T[offS + lane8 * 8];
    const float4* Td = (const float4*)&g_T[offD + lane8 * 8];
    float4 a0 = Ts[0], a1 = Ts[1];
    float4 c0 = Td[0], c1 = Td[1];
    float4 bb0 = *(const float4*)&sB1[lane8 * 8];
    float4 bb1 = *(const float4*)&sB1[lane8 * 8 + 4];
    float4 w0 = *(const float4*)&sW2[lane8 * 8];
    float4 w1 = *(const float4*)&sW2[lane8 * 8 + 4];

    float h0 = fmaxf(a0.x + c0.x + bb0.x, 0.0f);
    float h1 = fmaxf(a0.y + c0.y + bb0.y, 0.0f);
    float h2 = fmaxf(a0.z + c0.z + bb0.z, 0.0f);
    float h3 = fmaxf(a0.w + c0.w + bb0.w, 0.0f);
    float h4 = fmaxf(a1.x + c1.x + bb1.x, 0.0f);
    float h5 = fmaxf(a1.y + c1.y + bb1.y, 0.0f);
    float h6 = fmaxf(a1.z + c1.z + bb1.z, 0.0f);
    float h7 = fmaxf(a1.w + c1.w + bb1.w, 0.0f);
    float sum = h0 * w0.x + h1 * w0.y + h2 * w0.z + h3 * w0.w
              + h4 * w1.x + h5 * w1.y + h6 * w1.z + h7 * w1.w;

    sum += __shfl_down_sync(0xffffffffu, sum, 4, 8);
    sum += __shfl_down_sync(0xffffffffu, sum, 2, 8);
    sum += __shfl_down_sync(0xffffffffu, sum, 1, 8);

    if (lane8 == 0) out[e] = sum + __ldg(b2);
}

// ---------------------------------------------------------------------------
extern "C" void kernel_launch(void* const* d_in, const int* in_sizes, int n_in,
                              void* d_out, int out_size) {
    const float* node_emb = (const float*)d_in[0];
    const void*  eidx     = d_in[1];
    const float* W1       = (const float*)d_in[2];
    const float* b1       = (const float*)d_in[3];
    const float* W2       = (const float*)d_in[4];
    const float* b2       = (const float*)d_in[5];
    float*       out      = (float*)d_out;

    const int twoE = in_sizes[1];
    const int E = twoE / 2;

    const int smem = (128 * 128 + 32 * 128) * (int)sizeof(float);  // 80 KB
    cudaFuncSetAttribute(precompute_kernel,
                         cudaFuncAttributeMaxDynamicSharedMemorySize, smem);

    detect_kernel<<<1, 256>>>((const long long*)eidx, twoE);
    precompute_kernel<<<(NNODES + 31) / 32, 256, smem>>>(node_emb, W1);
    edge_kernel<<<(E + 31) / 32, 256>>>(eidx, b1, W2, b2, out, E);
}

// round 4
// speedup vs baseline: 1.2300x; 1.0161x over previous
#include <cuda_runtime.h>
#include <cuda_bf16.h>

#define NNODES 50000
#define HIDDEN 128
#define MLPD   64

// Per-node precomputed table: T[n][0:64]  = emb[n] @ W1[0:128,:],
//                             T[n][64:128]= emb[n] @ W1[128:256,:]
__device__ float g_T[(size_t)NNODES * HIDDEN];
__device__ int g_is64;   // 1 if edge_index buffer is int64, 0 if int32

// ---- packed f32x2 helpers (sm_100+ only via PTX) ---------------------------
__device__ __forceinline__ unsigned long long pk2(float lo, float hi) {
    unsigned long long r;
    asm("mov.b64 %0, {%1,%2};" : "=l"(r) : "f"(lo), "f"(hi));
    return r;
}
__device__ __forceinline__ unsigned long long fma2(unsigned long long a,
                                                   unsigned long long b,
                                                   unsigned long long c) {
    unsigned long long d;
    asm("fma.rn.f32x2 %0, %1, %2, %3;" : "=l"(d) : "l"(a), "l"(b), "l"(c));
    return d;
}
__device__ __forceinline__ void upk2(unsigned long long v, float& lo, float& hi) {
    asm("mov.b64 {%0,%1}, %2;" : "=f"(lo), "=f"(hi) : "l"(v));
}

// ---------------------------------------------------------------------------
// Kernel 1: T = emb @ Wc   where Wc[k][c] = (c<64) ? W1[k][c] : W1[128+k][c-64]
// 256 threads, tile = 32 nodes x 128 cols, reg tile 4 nodes x 4 cols, FFMA2.
// Block 0 additionally runs the edge-index dtype probe (deterministic,
// overlapped by the other blocks' GEMM work).
// ---------------------------------------------------------------------------
__global__ void __launch_bounds__(256, 2)
precompute_kernel(const float* __restrict__ emb, const float* __restrict__ W1,
                  const long long* __restrict__ eidx64, int twoE) {
    extern __shared__ float smem[];
    float* sW = smem;              // [128][128] k-major
    float* sE = smem + 128 * 128;  // [32][128]  node-major

    const int t = threadIdx.x;
    const int n0 = blockIdx.x * 32;

    // --- dtype probe (block 0 only): reading 1024 int64 words (8 KB) is
    // in-bounds under both int32 and int64 interpretations of the buffer.
    if (blockIdx.x == 0) {
        __shared__ int ok;
        if (t == 0) ok = 1;
        __syncthreads();
        int n = twoE < 1024 ? twoE : 1024;
        for (int i = t; i < n; i += 256) {
            long long v = eidx64[i];
            if (v < 0 || v >= NNODES) ok = 0;
        }
        __syncthreads();
        if (t == 0) g_is64 = ok;
    }

    // Wc loader, float4 vectorized: 4096 float4s
    for (int i = t; i < 128 * 32; i += 256) {
        int k = i >> 5, c4 = i & 31;
        const float* srcp = (c4 < 16) ? (W1 + k * MLPD + c4 * 4)
                                      : (W1 + (HIDDEN + k) * MLPD + (c4 - 16) * 4);
        ((float4*)sW)[i] = *(const float4*)srcp;
    }
    // emb tile loader, float4: 1024 float4s
    for (int i = t; i < 32 * 32; i += 256) {
        int node = i >> 5, c4 = i & 31;
        int gn = n0 + node;
        ((float4*)sE)[i] = (gn < NNODES)
            ? *(const float4*)&emb[(size_t)gn * HIDDEN + c4 * 4]
            : make_float4(0.f, 0.f, 0.f, 0.f);
    }
    __syncthreads();

    const int tx = t & 31;   // col group: cols tx*4 .. tx*4+3
    const int ty = t >> 5;   // node group: nodes ty*4 .. ty*4+3

    unsigned long long acc01[4], acc23[4];
    const unsigned long long z = pk2(0.f, 0.f);
#pragma unroll
    for (int i = 0; i < 4; i++) { acc01[i] = z; acc23[i] = z; }

#pragma unroll 4
    for (int k = 0; k < 128; k += 4) {
        float4 a[4], w[4];
#pragma unroll
        for (int i = 0; i < 4; i++)
            a[i] = *(const float4*)&sE[(ty * 4 + i) * 128 + k];
#pragma unroll
        for (int kk = 0; kk < 4; kk++)
            w[kk] = *(const float4*)&sW[(k + kk) * 128 + tx * 4];

        unsigned long long wlo[4], whi[4];
#pragma unroll
        for (int kk = 0; kk < 4; kk++) {
            wlo[kk] = pk2(w[kk].x, w[kk].y);
            whi[kk] = pk2(w[kk].z, w[kk].w);
        }
#pragma unroll
        for (int i = 0; i < 4; i++) {
            unsigned long long aa;
            aa = pk2(a[i].x, a[i].x);
            acc01[i] = fma2(aa, wlo[0], acc01[i]);
            acc23[i] = fma2(aa, whi[0], acc23[i]);
            aa = pk2(a[i].y, a[i].y);
            acc01[i] = fma2(aa, wlo[1], acc01[i]);
            acc23[i] = fma2(aa, whi[1], acc23[i]);
            aa = pk2(a[i].z, a[i].z);
            acc01[i] = fma2(aa, wlo[2], acc01[i]);
            acc23[i] = fma2(aa, whi[2], acc23[i]);
            aa = pk2(a[i].w, a[i].w);
            acc01[i] = fma2(aa, wlo[3], acc01[i]);
            acc23[i] = fma2(aa, whi[3], acc23[i]);
        }
    }

#pragma unroll
    for (int i = 0; i < 4; i++) {
        int gn = n0 + ty * 4 + i;
        if (gn < NNODES) {
            float4 v;
            upk2(acc01[i], v.x, v.y);
            upk2(acc23[i], v.z, v.w);
            *(float4*)&g_T[(size_t)gn * HIDDEN + tx * 4] = v;
        }
    }
}

// ---------------------------------------------------------------------------
// Kernel 2: per edge  logit = W2 . relu(T[src][0:64] + T[dst][64:128] + b1) + b2
// 8 threads per edge; each thread handles 8 contiguous h-columns (32B loads).
// All lanes of a group load the same two indices (L1 broadcast) — no shfl.
// ---------------------------------------------------------------------------
__global__ void __launch_bounds__(256)
edge_kernel(const void* __restrict__ eidx_raw,
            const float* __restrict__ b1, const float* __restrict__ W2,
            const float* __restrict__ b2, float* __restrict__ out, int E) {
    __shared__ float sB1[MLPD];
    __shared__ float sW2[MLPD];
    __shared__ float sB2;
    const int t = threadIdx.x;
    if (t < MLPD) sB1[t] = b1[t];
    else if (t < 2 * MLPD) sW2[t - MLPD] = W2[t - MLPD];
    else if (t == 2 * MLPD) sB2 = *b2;
    __syncthreads();

    const int lane8 = t & 7;
    const int e = blockIdx.x * 32 + (t >> 3);
    if (e >= E) return;

    int offS, offD;
    if (g_is64) {
        const long long* p = (const long long*)eidx_raw;
        offS = (int)p[e] * HIDDEN;
        offD = (int)p[(size_t)E + e] * HIDDEN + MLPD;
    } else {
        const int* p = (const int*)eidx_raw;
        offS = p[e] * HIDDEN;
        offD = p[E + e] * HIDDEN + MLPD;
    }

    const float4* Ts = (const float4*)&g_T[offS + lane8 * 8];
    const float4* Td = (const float4*)&g_T[offD + lane8 * 8];
    float4 a0 = Ts[0], a1 = Ts[1];
    float4 c0 = Td[0], c1 = Td[1];
    float4 bb0 = *(const float4*)&sB1[lane8 * 8];
    float4 bb1 = *(const float4*)&sB1[lane8 * 8 + 4];
    float4 w0 = *(const float4*)&sW2[lane8 * 8];
    float4 w1 = *(const float4*)&sW2[lane8 * 8 + 4];

    float h0 = fmaxf(a0.x + c0.x + bb0.x, 0.0f);
    float h1 = fmaxf(a0.y + c0.y + bb0.y, 0.0f);
    float h2 = fmaxf(a0.z + c0.z + bb0.z, 0.0f);
    float h3 = fmaxf(a0.w + c0.w + bb0.w, 0.0f);
    float h4 = fmaxf(a1.x + c1.x + bb1.x, 0.0f);
    float h5 = fmaxf(a1.y + c1.y + bb1.y, 0.0f);
    float h6 = fmaxf(a1.z + c1.z + bb1.z, 0.0f);
    float h7 = fmaxf(a1.w + c1.w + bb1.w, 0.0f);
    float sum = h0 * w0.x + h1 * w0.y + h2 * w0.z + h3 * w0.w
              + h4 * w1.x + h5 * w1.y + h6 * w1.z + h7 * w1.w;

    sum += __shfl_down_sync(0xffffffffu, sum, 4, 8);
    sum += __shfl_down_sync(0xffffffffu, sum, 2, 8);
    sum += __shfl_down_sync(0xffffffffu, sum, 1, 8);

    if (lane8 == 0) out[e] = sum + sB2;
}

// ---------------------------------------------------------------------------
extern "C" void kernel_launch(void* const* d_in, const int* in_sizes, int n_in,
                              void* d_out, int out_size) {
    const float* node_emb = (const float*)d_in[0];
    const void*  eidx     = d_in[1];
    const float* W1       = (const float*)d_in[2];
    const float* b1       = (const float*)d_in[3];
    const float* W2       = (const float*)d_in[4];
    const float* b2       = (const float*)d_in[5];
    float*       out      = (float*)d_out;

    const int twoE = in_sizes[1];
    const int E = twoE / 2;

    const int smem = (128 * 128 + 32 * 128) * (int)sizeof(float);  // 80 KB
    cudaFuncSetAttribute(precompute_kernel,
                         cudaFuncAttributeMaxDynamicSharedMemorySize, smem);

    precompute_kernel<<<(NNODES + 31) / 32, 256, smem>>>(
        node_emb, W1, (const long long*)eidx, twoE);
    edge_kernel<<<(E + 31) / 32, 256>>>(eidx, b1, W2, b2, out, E);
}

// round 5
// speedup vs baseline: 1.5147x; 1.2315x over previous
#include <cuda_runtime.h>
#include <cuda_bf16.h>

#define NNODES 50000
#define HIDDEN 128
#define MLPD   64

// Per-node precomputed table:
//   T[n][0:64]   = emb[n] @ W1[0:128,:]  + b1   (src half, bias folded in)
//   T[n][64:128] = emb[n] @ W1[128:256,:]       (dst half)
__device__ float g_T[(size_t)NNODES * HIDDEN];
__device__ int g_is64;   // 1 if edge_index buffer is int64, 0 if int32

// ---- packed f32x2 helpers (sm_100+ only via PTX) ---------------------------
__device__ __forceinline__ unsigned long long pk2(float lo, float hi) {
    unsigned long long r;
    asm("mov.b64 %0, {%1,%2};" : "=l"(r) : "f"(lo), "f"(hi));
    return r;
}
__device__ __forceinline__ unsigned long long fma2(unsigned long long a,
                                                   unsigned long long b,
                                                   unsigned long long c) {
    unsigned long long d;
    asm("fma.rn.f32x2 %0, %1, %2, %3;" : "=l"(d) : "l"(a), "l"(b), "l"(c));
    return d;
}
__device__ __forceinline__ void upk2(unsigned long long v, float& lo, float& hi) {
    asm("mov.b64 {%0,%1}, %2;" : "=f"(lo), "=f"(hi) : "l"(v));
}

// ---------------------------------------------------------------------------
// Kernel 1: T = emb @ Wc (+b1 on cols 0..63)
//   Wc[k][c] = (c<64) ? W1[k][c] : W1[128+k][c-64]
// Block tile: 128 nodes x 128 cols, 256 threads, thread tile 8 nodes x 8 cols.
// 16 LDS.128 feed 128 FFMA2 per k-quad (2x the FMA/LDS of the 4x4 tiling).
// Block 0 additionally runs the edge-index dtype probe.
// ---------------------------------------------------------------------------
__global__ void __launch_bounds__(256, 1)
precompute_kernel(const float* __restrict__ emb, const float* __restrict__ W1,
                  const float* __restrict__ b1,
                  const long long* __restrict__ eidx64, int twoE) {
    extern __shared__ float smem[];
    float* sW = smem;               // [128][128] k-major
    float* sE = smem + 128 * 128;   // [128][128] node-major

    const int t = threadIdx.x;
    const int n0 = blockIdx.x * 128;

    // --- dtype probe (block 0 only): 1024 int64 words (8 KB) is in-bounds
    // under both int32 and int64 interpretations of the buffer.
    if (blockIdx.x == 0) {
        __shared__ int ok;
        if (t == 0) ok = 1;
        __syncthreads();
        int n = twoE < 1024 ? twoE : 1024;
        for (int i = t; i < n; i += 256) {
            long long v = eidx64[i];
            if (v < 0 || v >= NNODES) ok = 0;
        }
        __syncthreads();
        if (t == 0) g_is64 = ok;
    }

    // Wc loader, float4: 4096 float4s
    for (int i = t; i < 128 * 32; i += 256) {
        int k = i >> 5, c4 = i & 31;
        const float* srcp = (c4 < 16) ? (W1 + k * MLPD + c4 * 4)
                                      : (W1 + (HIDDEN + k) * MLPD + (c4 - 16) * 4);
        ((float4*)sW)[i] = *(const float4*)srcp;
    }
    // emb tile loader, float4: 4096 float4s (node-major, coalesced)
    for (int i = t; i < 128 * 32; i += 256) {
        int node = i >> 5, c4 = i & 31;
        int gn = n0 + node;
        ((float4*)sE)[i] = (gn < NNODES)
            ? *(const float4*)&emb[(size_t)gn * HIDDEN + c4 * 4]
            : make_float4(0.f, 0.f, 0.f, 0.f);
    }
    __syncthreads();

    const int tx = t & 15;   // col group: cols tx*8 .. tx*8+7
    const int ty = t >> 4;   // node group: nodes ty*8 .. ty*8+7

    unsigned long long acc[8][4];
    const unsigned long long z = pk2(0.f, 0.f);
#pragma unroll
    for (int j = 0; j < 8; j++)
#pragma unroll
        for (int q = 0; q < 4; q++) acc[j][q] = z;

    for (int k0 = 0; k0 < 128; k0 += 4) {
        float4 a[8];
#pragma unroll
        for (int j = 0; j < 8; j++)
            a[j] = *(const float4*)&sE[(ty * 8 + j) * 128 + k0];
        const float* av = (const float*)a;   // av[j*4+kk]

#pragma unroll
        for (int kk = 0; kk < 4; kk++) {
            float4 wA = *(const float4*)&sW[(k0 + kk) * 128 + tx * 8];
            float4 wB = *(const float4*)&sW[(k0 + kk) * 128 + tx * 8 + 4];
            unsigned long long p0 = pk2(wA.x, wA.y);
            unsigned long long p1 = pk2(wA.z, wA.w);
            unsigned long long p2 = pk2(wB.x, wB.y);
            unsigned long long p3 = pk2(wB.z, wB.w);
#pragma unroll
            for (int j = 0; j < 8; j++) {
                float aj = av[j * 4 + kk];
                unsigned long long aa = pk2(aj, aj);
                acc[j][0] = fma2(aa, p0, acc[j][0]);
                acc[j][1] = fma2(aa, p1, acc[j][1]);
                acc[j][2] = fma2(aa, p2, acc[j][2]);
                acc[j][3] = fma2(aa, p3, acc[j][3]);
            }
        }
    }

    // Bias: fold b1 into cols 0..63 (src half)
    float bv[8];
    if (tx < 8) {
        float4 bA = *(const float4*)&b1[tx * 8];
        float4 bB = *(const float4*)&b1[tx * 8 + 4];
        bv[0] = bA.x; bv[1] = bA.y; bv[2] = bA.z; bv[3] = bA.w;
        bv[4] = bB.x; bv[5] = bB.y; bv[6] = bB.z; bv[7] = bB.w;
    } else {
#pragma unroll
        for (int q = 0; q < 8; q++) bv[q] = 0.f;
    }

#pragma unroll
    for (int j = 0; j < 8; j++) {
        int gn = n0 + ty * 8 + j;
        if (gn < NNODES) {
            float v[8];
            upk2(acc[j][0], v[0], v[1]);
            upk2(acc[j][1], v[2], v[3]);
            upk2(acc[j][2], v[4], v[5]);
            upk2(acc[j][3], v[6], v[7]);
            float4 o0 = make_float4(v[0] + bv[0], v[1] + bv[1], v[2] + bv[2], v[3] + bv[3]);
            float4 o1 = make_float4(v[4] + bv[4], v[5] + bv[5], v[6] + bv[6], v[7] + bv[7]);
            float* dst = &g_T[(size_t)gn * HIDDEN + tx * 8];
            *(float4*)dst = o0;
            *(float4*)(dst + 4) = o1;
        }
    }
}

// ---------------------------------------------------------------------------
// Kernel 2: per edge  logit = W2 . relu(T[src][0:64] + T[dst][64:128]) + b2
// 8 threads per edge. Lane l handles cols {4l..4l+3} u {32+4l..32+4l+3} so
// every gather instruction is 8 lanes x 16 B contiguous = one 128-B line.
// ---------------------------------------------------------------------------
__global__ void __launch_bounds__(256)
edge_kernel(const void* __restrict__ eidx_raw,
            const float* __restrict__ W2, const float* __restrict__ b2,
            float* __restrict__ out, int E) {
    __shared__ float sW2[MLPD];
    __shared__ float sB2;
    const int t = threadIdx.x;
    if (t < MLPD) sW2[t] = W2[t];
    else if (t == MLPD) sB2 = *b2;
    __syncthreads();

    const int lane8 = t & 7;
    const int e = blockIdx.x * 32 + (t >> 3);
    if (e >= E) return;

    int offS, offD;
    if (g_is64) {
        const long long* p = (const long long*)eidx_raw;
        offS = (int)p[e] * HIDDEN;
        offD = (int)p[(size_t)E + e] * HIDDEN + MLPD;
    } else {
        const int* p = (const int*)eidx_raw;
        offS = p[e] * HIDDEN;
        offD = p[E + e] * HIDDEN + MLPD;
    }

    const int c0i = lane8 * 4;        // cols 4l..4l+3
    const int c1i = 32 + lane8 * 4;   // cols 32+4l..32+4l+3
    float4 a0 = *(const float4*)&g_T[offS + c0i];
    float4 a1 = *(const float4*)&g_T[offS + c1i];
    float4 d0 = *(const float4*)&g_T[offD + c0i];
    float4 d1 = *(const float4*)&g_T[offD + c1i];
    float4 w0 = *(const float4*)&sW2[c0i];
    float4 w1 = *(const float4*)&sW2[c1i];

    float h0 = fmaxf(a0.x + d0.x, 0.0f);
    float h1 = fmaxf(a0.y + d0.y, 0.0f);
    float h2 = fmaxf(a0.z + d0.z, 0.0f);
    float h3 = fmaxf(a0.w + d0.w, 0.0f);
    float h4 = fmaxf(a1.x + d1.x, 0.0f);
    float h5 = fmaxf(a1.y + d1.y, 0.0f);
    float h6 = fmaxf(a1.z + d1.z, 0.0f);
    float h7 = fmaxf(a1.w + d1.w, 0.0f);
    float sum = h0 * w0.x + h1 * w0.y + h2 * w0.z + h3 * w0.w
              + h4 * w1.x + h5 * w1.y + h6 * w1.z + h7 * w1.w;

    sum += __shfl_down_sync(0xffffffffu, sum, 4, 8);
    sum += __shfl_down_sync(0xffffffffu, sum, 2, 8);
    sum += __shfl_down_sync(0xffffffffu, sum, 1, 8);

    if (lane8 == 0) out[e] = sum + sB2;
}

// ---------------------------------------------------------------------------
extern "C" void kernel_launch(void* const* d_in, const int* in_sizes, int n_in,
                              void* d_out, int out_size) {
    const float* node_emb = (const float*)d_in[0];
    const void*  eidx     = d_in[1];
    const float* W1       = (const float*)d_in[2];
    const float* b1       = (const float*)d_in[3];
    const float* W2       = (const float*)d_in[4];
    const float* b2       = (const float*)d_in[5];
    float*       out      = (float*)d_out;

    const int twoE = in_sizes[1];
    const int E = twoE / 2;

    const int smem = (128 * 128 * 2) * (int)sizeof(float);  // 128 KB
    cudaFuncSetAttribute(precompute_kernel,
                         cudaFuncAttributeMaxDynamicSharedMemorySize, smem);

    precompute_kernel<<<(NNODES + 127) / 128, 256, smem>>>(
        node_emb, W1, b1, (const long long*)eidx, twoE);
    edge_kernel<<<(E + 31) / 32, 256>>>(eidx, W2, b2, out, E);
}